// round 16
// baseline (speedup 1.0000x reference)
#include <cuda_runtime.h>
#include <cuda_bf16.h>
#include <math.h>
#include <stdint.h>

#define BBATCH 64
#define LLEN 128
#define TSTEPS 48
#define EDIM 512
#define HEDIM 1024
#define HDIM 1024
#define NCTA 148

typedef __nv_bfloat16 bf16;

// ---------------- device scratch ----------------
__device__ bf16 g_Wih1[4096 * 1024];
__device__ bf16 g_Whh1[4096 * 2048];
__device__ bf16 g_Wih2A[4096 * 2048];
__device__ bf16 g_Wih2B[4096 * 2048];
__device__ bf16 g_Whh2[4096 * 2048];
__device__ bf16 g_WcmA[1024 * 2048];
__device__ bf16 g_WcmB[1024 * 2048];
__device__ bf16 g_Watt[1024 * 2048];
__device__ bf16 g_enchl[8192 * 2048];
__device__ bf16 g_capshl[3072 * 1024];
__device__ float g_encproj[8192 * 1024];
__device__ float g_pregates[3072 * 4096];
__device__ float g_gpartA[BBATCH * 4096];
__device__ float g_gpartB[BBATCH * 4096];
__device__ float g_cpart[BBATCH * 1024];
__device__ float g_scores[BBATCH * LLEN];
__device__ bf16 g_h1hl[2][BBATCH * 2048];
__device__ bf16 g_h2hl[2][BBATCH * 2048];
__device__ bf16 g_ohl[BBATCH * 2048];
__device__ bf16 g_athl[BBATCH * 2048];
__device__ float g_c1[BBATCH * HDIM];
__device__ float g_c2[BBATCH * HDIM];
__device__ float g_h2f[BBATCH * HDIM];
__device__ float g_bg1[4096];
__device__ float g_bg2[4096];
__device__ float g_zero[4096];

__device__ unsigned g_cnt[256];
__device__ unsigned g_gen[256];

__device__ __forceinline__ float sigm(float x) { return 1.f / (1.f + __expf(-x)); }

#define CP16(dst, src) \
    asm volatile("cp.async.cg.shared.global [%0], [%1], 16;\n" ::"r"(dst), "l"(src))
#define LDSM4(R0, R1, R2, R3, ADDR)                                        \
    asm volatile("ldmatrix.sync.aligned.m8n8.x4.shared.b16 {%0,%1,%2,%3},[%4];\n" \
                 : "=r"(R0), "=r"(R1), "=r"(R2), "=r"(R3)                  \
                 : "r"(ADDR))
#define MMA16816(C, A0, A1, A2, A3, B0, B1)                                    \
    asm volatile(                                                               \
        "mma.sync.aligned.m16n8k16.row.col.f32.bf16.bf16.f32 "                  \
        "{%0,%1,%2,%3},{%4,%5,%6,%7},{%8,%9},{%0,%1,%2,%3};\n"                  \
        : "+f"((C)[0]), "+f"((C)[1]), "+f"((C)[2]), "+f"((C)[3])                \
        : "r"(A0), "r"(A1), "r"(A2), "r"(A3), "r"(B0), "r"(B1))

// ---------------- fused prologue conversions ----------------
__device__ __forceinline__ void conv_job(const float* __restrict__ src, int srcld,
                                         int colOff, int K, bf16* __restrict__ dst,
                                         int interleave, int N, int lb) {
    int idx = lb * 256 + threadIdx.x;
    if (idx >= N * K) return;
    int n = idx / K, k = idx - n * K;
    int srcn = interleave ? ((n & 3) * HDIM + (n >> 2)) : n;
    float v = src[(size_t)srcn * srcld + colOff + k];
    bf16 hi = __float2bfloat16(v);
    bf16 lo = __float2bfloat16(v - __bfloat162float(hi));
    dst[(size_t)n * 2 * K + k] = hi;
    dst[(size_t)n * 2 * K + K + k] = lo;
}

#define CONV_BLOCKS 125200

__global__ void conv_all(const float* __restrict__ enc, const float* __restrict__ cap,
                         const float* __restrict__ Wih1, const float* __restrict__ Whh1,
                         const float* __restrict__ Wih2, const float* __restrict__ Whh2,
                         const float* __restrict__ Wcomb, const float* __restrict__ Watt,
                         const float* __restrict__ bi1, const float* __restrict__ bh1,
                         const float* __restrict__ bi2, const float* __restrict__ bh2,
                         const float* __restrict__ h1i, const float* __restrict__ c1i,
                         const float* __restrict__ h2i, const float* __restrict__ c2i) {
    int b = blockIdx.x;
    if (b < 8192)        conv_job(Wih1, 512, 0, 512, g_Wih1, 1, 4096, b);
    else if (b < 24576)  conv_job(Whh1, 1024, 0, 1024, g_Whh1, 1, 4096, b - 8192);
    else if (b < 40960)  conv_job(Wih2, 2048, 0, 1024, g_Wih2A, 1, 4096, b - 24576);
    else if (b < 57344)  conv_job(Wih2, 2048, 1024, 1024, g_Wih2B, 1, 4096, b - 40960);
    else if (b < 73728)  conv_job(Whh2, 1024, 0, 1024, g_Whh2, 1, 4096, b - 57344);
    else if (b < 77824)  conv_job(Wcomb, 2048, 0, 1024, g_WcmA, 0, 1024, b - 73728);
    else if (b < 81920)  conv_job(Wcomb, 2048, 1024, 1024, g_WcmB, 0, 1024, b - 77824);
    else if (b < 86016)  conv_job(Watt, 1024, 0, 1024, g_Watt, 0, 1024, b - 81920);
    else if (b < 118784) conv_job(enc, 1024, 0, 1024, g_enchl, 0, 8192, b - 86016);
    else if (b < 124928) conv_job(cap, 512, 0, 512, g_capshl, 0, 3072, b - 118784);
    else if (b < 124944) {
        int n = (b - 124928) * 256 + threadIdx.x;
        if (n < 4096) {
            int srcn = (n & 3) * HDIM + (n >> 2);
            g_bg1[n] = bi1[srcn] + bh1[srcn];
            g_bg2[n] = bi2[srcn] + bh2[srcn];
            g_zero[n] = 0.f;
        }
    } else {
        int i = (b - 124944) * 256 + threadIdx.x;
        if (i < BBATCH * HDIM) {
            int bb = i >> 10, k = i & 1023;
            g_c1[i] = c1i[i];
            g_c2[i] = c2i[i];
            g_h2f[i] = h2i[i];
            float v1 = h1i[i];
            bf16 h = __float2bfloat16(v1);
            bf16 l = __float2bfloat16(v1 - __bfloat162float(h));
            g_h1hl[0][bb * 2048 + k] = h;
            g_h1hl[0][bb * 2048 + 1024 + k] = l;
            float v2 = h2i[i];
            h = __float2bfloat16(v2);
            l = __float2bfloat16(v2 - __bfloat162float(h));
            g_h2hl[0][bb * 2048 + k] = h;
            g_h2hl[0][bb * 2048 + 1024 + k] = l;
            bf16 z = __float2bfloat16(0.f);
            g_ohl[bb * 2048 + k] = z;
            g_ohl[bb * 2048 + 1024 + k] = z;
        }
    }
}

// ---------------- 64x64 GEMM mainloop (256 threads, dual accumulators) ----------------
#define STGB 32768
#define NSTG 4

__device__ __forceinline__ void gemm64(
    char* smem, int m0, int n0,
    const bf16* A0, const bf16* W0, int K0, float acc[4][4]) {
    const int tid = threadIdx.x;
    const int w = tid >> 5;
    const int l = tid & 31;
    const int wg = w >> 2;
    const int wm = w & 3;

    const int NCH = K0 >> 6;
    const uint32_t sB = (uint32_t)__cvta_generic_to_shared(smem);

    int ckt = 0;
    auto issue = [&](int stg) {
        const int ld = K0 << 1;
        const uint32_t base = sB + stg * STGB;
#pragma unroll
        for (int i = 0; i < 8; ++i) {
            int c = tid + (i << 8);
            if (c < 512) {
                int row = c >> 3, ch = c & 7;
                const bf16* src = A0 + (size_t)(m0 + row) * ld + ckt + (ch << 3);
                CP16(base + row * 128 + ((ch ^ (row & 7)) << 4), src);
            } else if (c < 1024) {
                int c2 = c - 512;
                int row = c2 >> 3, ch = c2 & 7;
                const bf16* src = A0 + (size_t)(m0 + row) * ld + K0 + ckt + (ch << 3);
                CP16(base + 8192 + row * 128 + ((ch ^ (row & 7)) << 4), src);
            } else if (c < 1536) {
                int c2 = c - 1024;
                int row = c2 >> 3, ch = c2 & 7;
                const bf16* src = W0 + (size_t)(n0 + row) * ld + ckt + (ch << 3);
                CP16(base + 16384 + row * 128 + ((ch ^ (row & 7)) << 4), src);
            } else {
                int c2 = c - 1536;
                int row = c2 >> 3, ch = c2 & 7;
                const bf16* src = W0 + (size_t)(n0 + row) * ld + K0 + ckt + (ch << 3);
                CP16(base + 24576 + row * 128 + ((ch ^ (row & 7)) << 4), src);
            }
        }
        asm volatile("cp.async.commit_group;\n" ::);
        ckt += 64;
    };

    float accA[4][4], accB[4][4];
#pragma unroll
    for (int j = 0; j < 4; ++j)
#pragma unroll
        for (int i = 0; i < 4; ++i) { accA[j][i] = 0.f; accB[j][i] = 0.f; }

    const int npre = (NCH < NSTG - 1) ? NCH : (NSTG - 1);
    for (int i = 0; i < npre; ++i) issue(i);

    const int arow = 16 * wm + (l & 15);
    const int asel = (l >> 4) & 1;
    const int nrow0 = wg * 32 + (l & 7) + ((l & 16) >> 1);
    const int nrow1 = nrow0 + 16;
    const int bsel = (l >> 3) & 1;

    for (int it = 0; it < NCH; ++it) {
        const int pend = ((NCH < it + NSTG - 1) ? NCH : (it + NSTG - 1)) - (it + 1);
        if (pend >= 2)      asm volatile("cp.async.wait_group 2;\n" ::);
        else if (pend == 1) asm volatile("cp.async.wait_group 1;\n" ::);
        else                asm volatile("cp.async.wait_group 0;\n" ::);
        __syncthreads();
        if (it + NSTG - 1 < NCH) issue((it + NSTG - 1) & (NSTG - 1));

        const uint32_t aHi = sB + (it & (NSTG - 1)) * STGB;
        const uint32_t aLo = aHi + 8192;
        const uint32_t wHi = aHi + 16384;
        const uint32_t wLo = aHi + 24576;
#pragma unroll
        for (int kh = 0; kh < 4; ++kh) {
            const int ac = 2 * kh + asel;
            const int bc = 2 * kh + bsel;
            const uint32_t aoff = arow * 128 + ((ac ^ (arow & 7)) << 4);
            const uint32_t boff0 = nrow0 * 128 + ((bc ^ (nrow0 & 7)) << 4);
            const uint32_t boff1 = nrow1 * 128 + ((bc ^ (nrow1 & 7)) << 4);
            uint32_t ah0, ah1, ah2, ah3, al0, al1, al2, al3;
            LDSM4(ah0, ah1, ah2, ah3, aHi + aoff);
            LDSM4(al0, al1, al2, al3, aLo + aoff);
            uint32_t bh0, bh1, bh2, bh3, bh4, bh5, bh6, bh7;
            LDSM4(bh0, bh1, bh2, bh3, wHi + boff0);
            LDSM4(bh4, bh5, bh6, bh7, wHi + boff1);
            uint32_t bl0, bl1, bl2, bl3, bl4, bl5, bl6, bl7;
            LDSM4(bl0, bl1, bl2, bl3, wLo + boff0);
            LDSM4(bl4, bl5, bl6, bl7, wLo + boff1);
            MMA16816(accA[0], ah0, ah1, ah2, ah3, bh0, bh1);
            MMA16816(accA[1], ah0, ah1, ah2, ah3, bh2, bh3);
            MMA16816(accA[2], ah0, ah1, ah2, ah3, bh4, bh5);
            MMA16816(accA[3], ah0, ah1, ah2, ah3, bh6, bh7);
            MMA16816(accB[0], ah0, ah1, ah2, ah3, bl0, bl1);
            MMA16816(accB[1], ah0, ah1, ah2, ah3, bl2, bl3);
            MMA16816(accB[2], ah0, ah1, ah2, ah3, bl4, bl5);
            MMA16816(accB[3], ah0, ah1, ah2, ah3, bl6, bl7);
            MMA16816(accB[0], al0, al1, al2, al3, bh0, bh1);
            MMA16816(accB[1], al0, al1, al2, al3, bh2, bh3);
            MMA16816(accB[2], al0, al1, al2, al3, bh4, bh5);
            MMA16816(accB[3], al0, al1, al2, al3, bh6, bh7);
        }
    }
#pragma unroll
    for (int j = 0; j < 4; ++j)
#pragma unroll
        for (int i = 0; i < 4; ++i) acc[j][i] = accA[j][i] + accB[j][i];
    __syncthreads();
}

// ---------------- epilogues ----------------
__device__ __forceinline__ void epi_store64(int m0, int n0, float acc[4][4],
                                            const float* biasV, float* outF, int ldo) {
    const int tid = threadIdx.x;
    const int w = tid >> 5, l = tid & 31;
    const int wg = w >> 2, wm = w & 3;
    const int r = l >> 2, c2 = (l & 3) * 2;
#pragma unroll
    for (int j = 0; j < 4; ++j) {
        int n = n0 + wg * 32 + 8 * j + c2;
        float bv0 = biasV[n], bv1 = biasV[n + 1];
        size_t row0 = (size_t)(m0 + 16 * wm + r);
        outF[row0 * ldo + n] = acc[j][0] + bv0;
        outF[row0 * ldo + n + 1] = acc[j][1] + bv1;
        outF[(row0 + 8) * ldo + n] = acc[j][2] + bv0;
        outF[(row0 + 8) * ldo + n + 1] = acc[j][3] + bv1;
    }
}

__device__ __forceinline__ void epi_lstm64(char* smem, int n0, float acc[4][4],
                                           const float* biasM1, const float* biasM2,
                                           int streamBias,
                                           bf16* outHL, float* outF, float* cstate) {
    const int tid = threadIdx.x;
    const int w = tid >> 5, l = tid & 31;
    const int wg = w >> 2, wm = w & 3;
    const int r = l >> 2, c2 = (l & 3) * 2;
    float* Csm = (float*)smem;
#pragma unroll
    for (int j = 0; j < 4; ++j) {
        int col = wg * 32 + 8 * j + c2;
        int n = n0 + col;
#pragma unroll
        for (int hh = 0; hh < 2; ++hh) {
            int m = 16 * wm + r + hh * 8;
            float b0, b1;
            if (streamBias) {
                b0 = __ldcs(&biasM1[(size_t)m * 4096 + n]);
                b1 = __ldcs(&biasM1[(size_t)m * 4096 + n + 1]);
            } else {
                b0 = __ldcg(&biasM1[(size_t)m * 4096 + n]);
                b1 = __ldcg(&biasM1[(size_t)m * 4096 + n + 1]);
            }
            if (biasM2) {
                b0 += __ldcg(&biasM2[(size_t)m * 4096 + n]);
                b1 += __ldcg(&biasM2[(size_t)m * 4096 + n + 1]);
            }
            Csm[m * 65 + col] = acc[j][2 * hh] + b0;
            Csm[m * 65 + col + 1] = acc[j][2 * hh + 1] + b1;
        }
    }
    __syncthreads();
#pragma unroll
    for (int q = 0; q < 4; ++q) {
        int item = tid * 4 + q;
        int b = item >> 4;
        int hu = item & 15;
        float gi = Csm[b * 65 + hu * 4 + 0];
        float gf = Csm[b * 65 + hu * 4 + 1];
        float gg = Csm[b * 65 + hu * 4 + 2];
        float go = Csm[b * 65 + hu * 4 + 3];
        int hg = (n0 >> 2) + hu;
        int idx = b * HDIM + hg;
        float cold = cstate[idx];
        float i_ = sigm(gi), f_ = sigm(gf), g_ = tanhf(gg), o_ = sigm(go);
        float cn = f_ * cold + i_ * g_;
        cstate[idx] = cn;
        float hv = o_ * tanhf(cn);
        if (outF) outF[idx] = hv;
        bf16 hi = __float2bfloat16(hv);
        bf16 lo = __float2bfloat16(hv - __bfloat162float(hi));
        outHL[b * 2048 + hg] = hi;
        outHL[b * 2048 + 1024 + hg] = lo;
    }
    __syncthreads();
}

__device__ __forceinline__ void epi_tanh_c(int n0, float acc[4][4], const float* cpartM,
                                           float* outF, int ldo, bf16* outHL) {
    const int tid = threadIdx.x;
    const int w = tid >> 5, l = tid & 31;
    const int wg = w >> 2, wm = w & 3;
    const int r = l >> 2, c2 = (l & 3) * 2;
#pragma unroll
    for (int j = 0; j < 4; ++j) {
        int n = n0 + wg * 32 + 8 * j + c2;
        int b0r = 16 * wm + r;
#pragma unroll
        for (int hh = 0; hh < 2; ++hh) {
            int bb = b0r + hh * 8;
            float p0 = __ldcg(&cpartM[(size_t)bb * 1024 + n]);
            float p1 = __ldcg(&cpartM[(size_t)bb * 1024 + n + 1]);
            float v0 = tanhf(acc[j][2 * hh] + p0);
            float v1 = tanhf(acc[j][2 * hh + 1] + p1);
            __stcs(&outF[(size_t)bb * ldo + n], v0);
            __stcs(&outF[(size_t)bb * ldo + n + 1], v1);
            bf16 h0 = __float2bfloat16(v0);
            bf16 l0 = __float2bfloat16(v0 - __bfloat162float(h0));
            bf16 h1 = __float2bfloat16(v1);
            bf16 l1 = __float2bfloat16(v1 - __bfloat162float(h1));
            outHL[bb * 2048 + n] = h0;
            outHL[bb * 2048 + 1024 + n] = l0;
            outHL[bb * 2048 + n + 1] = h1;
            outHL[bb * 2048 + 1024 + n + 1] = l1;
        }
    }
}

// ---------------- attention split: scores (phase B) + context (phase C) ----------------
#define ATT_STG 32768

// scores for rows [half*64, half*64+64) of batch b -> g_scores (masked)
__device__ __forceinline__ void attn_scores(char* smem, int b, int half,
                                            const int* __restrict__ masks,
                                            const float* __restrict__ encproj,
                                            const float* __restrict__ h2f,
                                            float* __restrict__ scores) {
    float* sh2 = (float*)(smem + 3 * ATT_STG);
    const int tid = threadIdx.x;
    const int w = tid >> 5, l = tid & 31;
    const uint32_t sB = (uint32_t)__cvta_generic_to_shared(smem);

    {
        const float4* src = (const float4*)(h2f + b * HDIM);
        ((float4*)sh2)[tid] = __ldcg(src + tid);
    }

    const char* epbase = (const char*)(encproj + ((size_t)b * LLEN + half * 64) * HDIM);
    auto issueS = [&](int s) {
        const uint32_t base = sB + (s % 3) * ATT_STG;
        const char* src = epbase + (size_t)s * ATT_STG;
#pragma unroll
        for (int i = 0; i < 8; ++i) {
            int c = tid + (i << 8);
            CP16(base + c * 16, src + c * 16);
        }
        asm volatile("cp.async.commit_group;\n" ::);
    };
    issueS(0); issueS(1); issueS(2);
    __syncthreads();

    const float4* sh4 = (const float4*)sh2;
    for (int s = 0; s < 8; ++s) {
        if (s <= 5)      asm volatile("cp.async.wait_group 2;\n" ::);
        else if (s == 6) asm volatile("cp.async.wait_group 1;\n" ::);
        else             asm volatile("cp.async.wait_group 0;\n" ::);
        __syncthreads();
        const float4* row = (const float4*)(smem + (s % 3) * ATT_STG + w * 4096);
        float sdot = 0.f;
#pragma unroll
        for (int j = 0; j < 8; ++j) {
            float4 hv = sh4[l + 32 * j];
            float4 ev = row[l + 32 * j];
            sdot += hv.x * ev.x + hv.y * ev.y + hv.z * ev.z + hv.w * ev.w;
        }
#pragma unroll
        for (int o = 16; o; o >>= 1) sdot += __shfl_xor_sync(0xffffffffu, sdot, o);
        if (l == 0) {
            int ll = half * 64 + s * 8 + w;
            scores[b * LLEN + ll] = masks[b * LLEN + ll] ? -1e30f : sdot;
        }
        __syncthreads();
        if (s + 3 < 8) issueS(s + 3);
    }
}

// softmax (from g_scores) + context stream + athl hi/lo
__device__ __forceinline__ void attn_context(char* smem, int b,
                                             const float* __restrict__ scores,
                                             const float* __restrict__ enc,
                                             bf16* __restrict__ athl) {
    float* sred = (float*)(smem + 3 * ATT_STG + 4096);
    float* salpha = sred + LLEN;
    float* stmp = salpha + LLEN;
    const int tid = threadIdx.x;
    const uint32_t sB = (uint32_t)__cvta_generic_to_shared(smem);

    if (tid < 128) {
        float v = __ldcg(&scores[b * LLEN + tid]);
        sred[tid] = v;
        stmp[tid] = v;
    }
    __syncthreads();
    for (int s = 64; s; s >>= 1) {
        if (tid < s) stmp[tid] = fmaxf(stmp[tid], stmp[tid + s]);
        __syncthreads();
    }
    const float mx = stmp[0];
    __syncthreads();
    if (tid < 128) {
        float p = __expf(sred[tid] - mx);
        salpha[tid] = p;
        stmp[tid] = p;
    }
    __syncthreads();
    for (int s = 64; s; s >>= 1) {
        if (tid < s) stmp[tid] += stmp[tid + s];
        __syncthreads();
    }
    const float inv = 1.f / stmp[0];
    __syncthreads();
    if (tid < 128) salpha[tid] *= inv;
    __syncthreads();

    const char* enbase = (const char*)(enc + (size_t)b * LLEN * HEDIM);
    auto issueC = [&](int s) {
        const uint32_t base = sB + (s % 3) * ATT_STG;
        const char* src = enbase + (size_t)s * ATT_STG;
#pragma unroll
        for (int i = 0; i < 8; ++i) {
            int c = tid + (i << 8);
            CP16(base + c * 16, src + c * 16);
        }
        asm volatile("cp.async.commit_group;\n" ::);
    };
    issueC(0); issueC(1); issueC(2);

    float4 accv = make_float4(0.f, 0.f, 0.f, 0.f);
    for (int s = 0; s < 16; ++s) {
        if (s <= 13)      asm volatile("cp.async.wait_group 2;\n" ::);
        else if (s == 14) asm volatile("cp.async.wait_group 1;\n" ::);
        else              asm volatile("cp.async.wait_group 0;\n" ::);
        __syncthreads();
        const float4* stage4 = (const float4*)(smem + (s % 3) * ATT_STG);
#pragma unroll
        for (int rrow = 0; rrow < 8; ++rrow) {
            float al = salpha[s * 8 + rrow];
            float4 v = stage4[rrow * 256 + tid];
            accv.x += al * v.x;
            accv.y += al * v.y;
            accv.z += al * v.z;
            accv.w += al * v.w;
        }
        __syncthreads();
        if (s + 3 < 16) issueC(s + 3);
    }

    int f = tid * 4;
    float vals[4] = {accv.x, accv.y, accv.z, accv.w};
#pragma unroll
    for (int i = 0; i < 4; ++i) {
        bf16 hi = __float2bfloat16(vals[i]);
        bf16 lo = __float2bfloat16(vals[i] - __bfloat162float(hi));
        athl[b * 2048 + f + i] = hi;
        athl[b * 2048 + 1024 + f + i] = lo;
    }
    __syncthreads();
}

// ---------------- grid barrier ----------------
__device__ __forceinline__ void gsync(int slot) {
    __threadfence();
    __syncthreads();
    if (threadIdx.x == 0) {
        unsigned g = ((volatile unsigned*)g_gen)[slot];
        unsigned old = atomicAdd(&g_cnt[slot], 1u);
        if (old == NCTA - 1) {
            g_cnt[slot] = 0;
            __threadfence();
            atomicExch(&g_gen[slot], g + 1);
        } else {
            while (((volatile unsigned*)g_gen)[slot] == g) __nanosleep(32);
        }
    }
    __syncthreads();
    __threadfence();
}

// ---------------- prologue GEMM ----------------
__global__ __launch_bounds__(256) void mma_pro(
    const bf16* A0, const bf16* W0, int K0,
    const float* __restrict__ biasV, float* __restrict__ outF, int ldo) {
    extern __shared__ __align__(16) char smem[];
    float acc[4][4];
    gemm64(smem, blockIdx.y * 64, blockIdx.x * 64, A0, W0, K0, acc);
    epi_store64(blockIdx.y * 64, blockIdx.x * 64, acc, biasV, outF, ldo);
}

// ---------------- step-phase helpers ----------------
__device__ __forceinline__ void lstm1_tile(char* smem, int tp, int tile) {
    float acc[4][4];
    int n0 = tile * 64;
    gemm64(smem, 0, n0, g_h1hl[tp & 1], g_Whh1, 1024, acc);
    epi_lstm64(smem, n0, acc, g_pregates + (size_t)tp * BBATCH * 4096, nullptr, 1,
               g_h1hl[(tp & 1) ^ 1], nullptr, g_c1);
}

__device__ __forceinline__ void lstm2_pair1(char* smem, int tp, int tile) {
    float acc[4][4];
    int n0 = tile * 64;
    gemm64(smem, 0, n0, g_h1hl[(tp & 1) ^ 1], g_Wih2A, 1024, acc);
    epi_store64(0, n0, acc, g_bg2, g_gpartA, 4096);
}

__device__ __forceinline__ void lstm2_pair2(char* smem, int tp, int tile) {
    float acc[4][4];
    int n0 = tile * 64;
    gemm64(smem, 0, n0, g_h2hl[tp & 1], g_Whh2, 1024, acc);
    epi_store64(0, n0, acc, g_zero, g_gpartB, 4096);
}

__device__ __forceinline__ void lstm2_final(char* smem, int t, int tile) {
    float acc[4][4];
    int n0 = tile * 64;
    gemm64(smem, 0, n0, g_ohl, g_Wih2B, 1024, acc);
    epi_lstm64(smem, n0, acc, g_gpartA, g_gpartB, 0, g_h2hl[(t + 1) & 1], g_h2f, g_c2);
}

__device__ __forceinline__ void comb_partial_b(char* smem, int t, int tile,
                                               const float* b_comb) {
    float acc[4][4];
    int n0 = tile * 64;
    gemm64(smem, 0, n0, g_h2hl[(t + 1) & 1], g_WcmB, 1024, acc);
    epi_store64(0, n0, acc, b_comb, g_cpart, 1024);
}

__device__ __forceinline__ void comb_final(char* smem, int t, int tile, float* outs) {
    float acc[4][4];
    int n0 = tile * 64;
    gemm64(smem, 0, n0, g_athl, g_WcmA, 1024, acc);
    epi_tanh_c(n0, acc, g_cpart, outs + (size_t)t * BBATCH * HDIM, 1024, g_ohl);
}

// ---------------- persistent decoder loop (4 phases/step) ----------------
__global__ __launch_bounds__(256, 1) void decoder_loop(
    const int* __restrict__ masks, const float* __restrict__ enc,
    const float* __restrict__ b_comb, float* __restrict__ outs) {
    extern __shared__ __align__(16) char smem[];
    const int bid = blockIdx.x;
    float* pScores;
    {
        pScores = g_scores;  // symbol in device code
    }

    if (bid < 64) lstm1_tile(smem, 0, bid);
    gsync(0);
    if (bid < 64) lstm2_pair1(smem, 0, bid);
    else if (bid < 128) lstm2_pair2(smem, 0, bid - 64);
    gsync(1);

    for (int t = 0; t < TSTEPS; ++t) {
        // PHASE A: lstm2_final@t (0-63) || lstm1@t+1 (64-127)
        if (bid < 64) {
            lstm2_final(smem, t, bid);
        } else if (bid < 128 && t + 1 < TSTEPS) {
            lstm1_tile(smem, t + 1, bid - 64);
        }
        gsync(2 + t * 4);

        // PHASE B: scores@t (0-127: b=bid>>1, half=bid&1) || comb-partial@t (128-143)
        if (bid < 128) {
            attn_scores(smem, bid >> 1, bid & 1, masks, g_encproj, g_h2f, pScores);
        } else if (bid < 144) {
            comb_partial_b(smem, t, bid - 128, b_comb);
        }
        gsync(3 + t * 4);

        // PHASE C: softmax+context@t (0-63) || pair1@t+1 (64-127)
        if (bid < 64) {
            attn_context(smem, bid, pScores, enc, g_athl);
        } else if (bid < 128 && t + 1 < TSTEPS) {
            lstm2_pair1(smem, t + 1, bid - 64);
        }
        gsync(4 + t * 4);

        // PHASE D: comb-final@t (0-15) || pair2@t+1 (16-79)
        if (bid < 16) {
            comb_final(smem, t, bid, outs);
        } else if (bid < 80 && t + 1 < TSTEPS) {
            lstm2_pair2(smem, t + 1, bid - 16);
        }
        gsync(5 + t * 4);
    }
}

// ---------------- host launcher ----------------
extern "C" void kernel_launch(void* const* d_in, const int* in_sizes, int n_in,
                              void* d_out, int out_size) {
    const float* enc = (const float*)d_in[0];
    const int* masks = (const int*)d_in[1];
    const float* h1i = (const float*)d_in[2];
    const float* c1i = (const float*)d_in[3];
    const float* h2i = (const float*)d_in[4];
    const float* c2i = (const float*)d_in[5];
    const float* cap = (const float*)d_in[6];
    const float* W_ih1 = (const float*)d_in[7];
    const float* W_hh1 = (const float*)d_in[8];
    const float* b_ih1 = (const float*)d_in[9];
    const float* b_hh1 = (const float*)d_in[10];
    const float* W_ih2 = (const float*)d_in[11];
    const float* W_hh2 = (const float*)d_in[12];
    const float* b_ih2 = (const float*)d_in[13];
    const float* b_hh2 = (const float*)d_in[14];
    const float* W_att = (const float*)d_in[15];
    const float* b_att = (const float*)d_in[16];
    const float* W_comb = (const float*)d_in[17];
    const float* b_comb = (const float*)d_in[18];
    float* outs = (float*)d_out;

    bf16 *pWih1, *pWatt, *pEnchl, *pCapshl;
    float *pEncproj, *pPre, *pBg1;
    cudaGetSymbolAddress((void**)&pWih1, g_Wih1);
    cudaGetSymbolAddress((void**)&pWatt, g_Watt);
    cudaGetSymbolAddress((void**)&pEnchl, g_enchl);
    cudaGetSymbolAddress((void**)&pCapshl, g_capshl);
    cudaGetSymbolAddress((void**)&pEncproj, g_encproj);
    cudaGetSymbolAddress((void**)&pPre, g_pregates);
    cudaGetSymbolAddress((void**)&pBg1, g_bg1);

    const int SMEM = NSTG * STGB;   // 128 KB
    cudaFuncSetAttribute(mma_pro, cudaFuncAttributeMaxDynamicSharedMemorySize, SMEM);
    cudaFuncSetAttribute(decoder_loop, cudaFuncAttributeMaxDynamicSharedMemorySize, SMEM);

    conv_all<<<CONV_BLOCKS, 256>>>(enc, cap, W_ih1, W_hh1, W_ih2, W_hh2, W_comb, W_att,
                                   b_ih1, b_hh1, b_ih2, b_hh2, h1i, c1i, h2i, c2i);

    mma_pro<<<dim3(64, 48), 256, SMEM>>>(pCapshl, pWih1, 512, pBg1, pPre, 4096);
    mma_pro<<<dim3(16, 128), 256, SMEM>>>(pEnchl, pWatt, 1024, b_att, pEncproj, 1024);

    decoder_loop<<<NCTA, 256, SMEM>>>(masks, enc, b_comb, outs);
}

// round 17
// speedup vs baseline: 1.1683x; 1.1683x over previous
#include <cuda_runtime.h>
#include <cuda_bf16.h>
#include <math.h>
#include <stdint.h>

#define BBATCH 64
#define LLEN 128
#define TSTEPS 48
#define EDIM 512
#define HEDIM 1024
#define HDIM 1024
#define NCTA 148

typedef __nv_bfloat16 bf16;

// ---------------- device scratch ----------------
__device__ bf16 g_Wih1[4096 * 1024];
__device__ bf16 g_Whh1[4096 * 2048];
__device__ bf16 g_Wih2A[4096 * 2048];
__device__ bf16 g_Wih2B[4096 * 2048];
__device__ bf16 g_Whh2[4096 * 2048];
__device__ bf16 g_WcmA[1024 * 2048];
__device__ bf16 g_WcmB[1024 * 2048];
__device__ bf16 g_Watt[1024 * 2048];
__device__ bf16 g_enchl[8192 * 2048];
__device__ bf16 g_capshl[3072 * 1024];
__device__ float g_encproj[8192 * 1024];
__device__ float g_pregates[3072 * 4096];
__device__ float g_gpartA[BBATCH * 4096];
__device__ float g_gpartB[BBATCH * 4096];
__device__ float g_cpart[BBATCH * 1024];
__device__ bf16 g_h1hl[2][BBATCH * 2048];
__device__ bf16 g_h2hl[2][BBATCH * 2048];
__device__ bf16 g_ohl[BBATCH * 2048];
__device__ bf16 g_athl[BBATCH * 2048];
__device__ float g_c1[BBATCH * HDIM];
__device__ float g_c2[BBATCH * HDIM];
__device__ float g_h2f[BBATCH * HDIM];
__device__ float g_bg1[4096];
__device__ float g_bg2[4096];
__device__ float g_zero[4096];

__device__ unsigned g_cnt[256];
__device__ unsigned g_gen[256];

__device__ __forceinline__ float sigm(float x) { return 1.f / (1.f + __expf(-x)); }

#define CP16(dst, src) \
    asm volatile("cp.async.cg.shared.global [%0], [%1], 16;\n" ::"r"(dst), "l"(src))
#define LDSM4(R0, R1, R2, R3, ADDR)                                        \
    asm volatile("ldmatrix.sync.aligned.m8n8.x4.shared.b16 {%0,%1,%2,%3},[%4];\n" \
                 : "=r"(R0), "=r"(R1), "=r"(R2), "=r"(R3)                  \
                 : "r"(ADDR))
#define MMA16816(C, A0, A1, A2, A3, B0, B1)                                    \
    asm volatile(                                                               \
        "mma.sync.aligned.m16n8k16.row.col.f32.bf16.bf16.f32 "                  \
        "{%0,%1,%2,%3},{%4,%5,%6,%7},{%8,%9},{%0,%1,%2,%3};\n"                  \
        : "+f"((C)[0]), "+f"((C)[1]), "+f"((C)[2]), "+f"((C)[3])                \
        : "r"(A0), "r"(A1), "r"(A2), "r"(A3), "r"(B0), "r"(B1))

// ---------------- fused prologue conversions ----------------
__device__ __forceinline__ void conv_job(const float* __restrict__ src, int srcld,
                                         int colOff, int K, bf16* __restrict__ dst,
                                         int interleave, int N, int lb) {
    int idx = lb * 256 + threadIdx.x;
    if (idx >= N * K) return;
    int n = idx / K, k = idx - n * K;
    int srcn = interleave ? ((n & 3) * HDIM + (n >> 2)) : n;
    float v = src[(size_t)srcn * srcld + colOff + k];
    bf16 hi = __float2bfloat16(v);
    bf16 lo = __float2bfloat16(v - __bfloat162float(hi));
    dst[(size_t)n * 2 * K + k] = hi;
    dst[(size_t)n * 2 * K + K + k] = lo;
}

#define CONV_BLOCKS 125200

__global__ void conv_all(const float* __restrict__ enc, const float* __restrict__ cap,
                         const float* __restrict__ Wih1, const float* __restrict__ Whh1,
                         const float* __restrict__ Wih2, const float* __restrict__ Whh2,
                         const float* __restrict__ Wcomb, const float* __restrict__ Watt,
                         const float* __restrict__ bi1, const float* __restrict__ bh1,
                         const float* __restrict__ bi2, const float* __restrict__ bh2,
                         const float* __restrict__ h1i, const float* __restrict__ c1i,
                         const float* __restrict__ h2i, const float* __restrict__ c2i) {
    int b = blockIdx.x;
    if (b < 8192)        conv_job(Wih1, 512, 0, 512, g_Wih1, 1, 4096, b);
    else if (b < 24576)  conv_job(Whh1, 1024, 0, 1024, g_Whh1, 1, 4096, b - 8192);
    else if (b < 40960)  conv_job(Wih2, 2048, 0, 1024, g_Wih2A, 1, 4096, b - 24576);
    else if (b < 57344)  conv_job(Wih2, 2048, 1024, 1024, g_Wih2B, 1, 4096, b - 40960);
    else if (b < 73728)  conv_job(Whh2, 1024, 0, 1024, g_Whh2, 1, 4096, b - 57344);
    else if (b < 77824)  conv_job(Wcomb, 2048, 0, 1024, g_WcmA, 0, 1024, b - 73728);
    else if (b < 81920)  conv_job(Wcomb, 2048, 1024, 1024, g_WcmB, 0, 1024, b - 77824);
    else if (b < 86016)  conv_job(Watt, 1024, 0, 1024, g_Watt, 0, 1024, b - 81920);
    else if (b < 118784) conv_job(enc, 1024, 0, 1024, g_enchl, 0, 8192, b - 86016);
    else if (b < 124928) conv_job(cap, 512, 0, 512, g_capshl, 0, 3072, b - 118784);
    else if (b < 124944) {
        int n = (b - 124928) * 256 + threadIdx.x;
        if (n < 4096) {
            int srcn = (n & 3) * HDIM + (n >> 2);
            g_bg1[n] = bi1[srcn] + bh1[srcn];
            g_bg2[n] = bi2[srcn] + bh2[srcn];
            g_zero[n] = 0.f;
        }
    } else {
        int i = (b - 124944) * 256 + threadIdx.x;
        if (i < BBATCH * HDIM) {
            int bb = i >> 10, k = i & 1023;
            g_c1[i] = c1i[i];
            g_c2[i] = c2i[i];
            g_h2f[i] = h2i[i];
            float v1 = h1i[i];
            bf16 h = __float2bfloat16(v1);
            bf16 l = __float2bfloat16(v1 - __bfloat162float(h));
            g_h1hl[0][bb * 2048 + k] = h;
            g_h1hl[0][bb * 2048 + 1024 + k] = l;
            float v2 = h2i[i];
            h = __float2bfloat16(v2);
            l = __float2bfloat16(v2 - __bfloat162float(h));
            g_h2hl[0][bb * 2048 + k] = h;
            g_h2hl[0][bb * 2048 + 1024 + k] = l;
            bf16 z = __float2bfloat16(0.f);
            g_ohl[bb * 2048 + k] = z;
            g_ohl[bb * 2048 + 1024 + k] = z;
        }
    }
}

// ---------------- 64x64 GEMM mainloop (256 threads, dual accumulators) ----------------
#define STGB 32768
#define NSTG 4

__device__ __forceinline__ void gemm64(
    char* smem, int m0, int n0,
    const bf16* A0, const bf16* W0, int K0, float acc[4][4]) {
    const int tid = threadIdx.x;
    const int w = tid >> 5;
    const int l = tid & 31;
    const int wg = w >> 2;
    const int wm = w & 3;

    const int NCH = K0 >> 6;
    const uint32_t sB = (uint32_t)__cvta_generic_to_shared(smem);

    int ckt = 0;
    auto issue = [&](int stg) {
        const int ld = K0 << 1;
        const uint32_t base = sB + stg * STGB;
#pragma unroll
        for (int i = 0; i < 8; ++i) {
            int c = tid + (i << 8);
            if (c < 512) {
                int row = c >> 3, ch = c & 7;
                const bf16* src = A0 + (size_t)(m0 + row) * ld + ckt + (ch << 3);
                CP16(base + row * 128 + ((ch ^ (row & 7)) << 4), src);
            } else if (c < 1024) {
                int c2 = c - 512;
                int row = c2 >> 3, ch = c2 & 7;
                const bf16* src = A0 + (size_t)(m0 + row) * ld + K0 + ckt + (ch << 3);
                CP16(base + 8192 + row * 128 + ((ch ^ (row & 7)) << 4), src);
            } else if (c < 1536) {
                int c2 = c - 1024;
                int row = c2 >> 3, ch = c2 & 7;
                const bf16* src = W0 + (size_t)(n0 + row) * ld + ckt + (ch << 3);
                CP16(base + 16384 + row * 128 + ((ch ^ (row & 7)) << 4), src);
            } else {
                int c2 = c - 1536;
                int row = c2 >> 3, ch = c2 & 7;
                const bf16* src = W0 + (size_t)(n0 + row) * ld + K0 + ckt + (ch << 3);
                CP16(base + 24576 + row * 128 + ((ch ^ (row & 7)) << 4), src);
            }
        }
        asm volatile("cp.async.commit_group;\n" ::);
        ckt += 64;
    };

    float accA[4][4], accB[4][4];
#pragma unroll
    for (int j = 0; j < 4; ++j)
#pragma unroll
        for (int i = 0; i < 4; ++i) { accA[j][i] = 0.f; accB[j][i] = 0.f; }

    const int npre = (NCH < NSTG - 1) ? NCH : (NSTG - 1);
    for (int i = 0; i < npre; ++i) issue(i);

    const int arow = 16 * wm + (l & 15);
    const int asel = (l >> 4) & 1;
    const int nrow0 = wg * 32 + (l & 7) + ((l & 16) >> 1);
    const int nrow1 = nrow0 + 16;
    const int bsel = (l >> 3) & 1;

    for (int it = 0; it < NCH; ++it) {
        const int pend = ((NCH < it + NSTG - 1) ? NCH : (it + NSTG - 1)) - (it + 1);
        if (pend >= 2)      asm volatile("cp.async.wait_group 2;\n" ::);
        else if (pend == 1) asm volatile("cp.async.wait_group 1;\n" ::);
        else                asm volatile("cp.async.wait_group 0;\n" ::);
        __syncthreads();
        if (it + NSTG - 1 < NCH) issue((it + NSTG - 1) & (NSTG - 1));

        const uint32_t aHi = sB + (it & (NSTG - 1)) * STGB;
        const uint32_t aLo = aHi + 8192;
        const uint32_t wHi = aHi + 16384;
        const uint32_t wLo = aHi + 24576;
#pragma unroll
        for (int kh = 0; kh < 4; ++kh) {
            const int ac = 2 * kh + asel;
            const int bc = 2 * kh + bsel;
            const uint32_t aoff = arow * 128 + ((ac ^ (arow & 7)) << 4);
            const uint32_t boff0 = nrow0 * 128 + ((bc ^ (nrow0 & 7)) << 4);
            const uint32_t boff1 = nrow1 * 128 + ((bc ^ (nrow1 & 7)) << 4);
            uint32_t ah0, ah1, ah2, ah3, al0, al1, al2, al3;
            LDSM4(ah0, ah1, ah2, ah3, aHi + aoff);
            LDSM4(al0, al1, al2, al3, aLo + aoff);
            uint32_t bh0, bh1, bh2, bh3, bh4, bh5, bh6, bh7;
            LDSM4(bh0, bh1, bh2, bh3, wHi + boff0);
            LDSM4(bh4, bh5, bh6, bh7, wHi + boff1);
            uint32_t bl0, bl1, bl2, bl3, bl4, bl5, bl6, bl7;
            LDSM4(bl0, bl1, bl2, bl3, wLo + boff0);
            LDSM4(bl4, bl5, bl6, bl7, wLo + boff1);
            MMA16816(accA[0], ah0, ah1, ah2, ah3, bh0, bh1);
            MMA16816(accA[1], ah0, ah1, ah2, ah3, bh2, bh3);
            MMA16816(accA[2], ah0, ah1, ah2, ah3, bh4, bh5);
            MMA16816(accA[3], ah0, ah1, ah2, ah3, bh6, bh7);
            MMA16816(accB[0], ah0, ah1, ah2, ah3, bl0, bl1);
            MMA16816(accB[1], ah0, ah1, ah2, ah3, bl2, bl3);
            MMA16816(accB[2], ah0, ah1, ah2, ah3, bl4, bl5);
            MMA16816(accB[3], ah0, ah1, ah2, ah3, bl6, bl7);
            MMA16816(accB[0], al0, al1, al2, al3, bh0, bh1);
            MMA16816(accB[1], al0, al1, al2, al3, bh2, bh3);
            MMA16816(accB[2], al0, al1, al2, al3, bh4, bh5);
            MMA16816(accB[3], al0, al1, al2, al3, bh6, bh7);
        }
    }
#pragma unroll
    for (int j = 0; j < 4; ++j)
#pragma unroll
        for (int i = 0; i < 4; ++i) acc[j][i] = accA[j][i] + accB[j][i];
    __syncthreads();
}

// ---------------- epilogues ----------------
__device__ __forceinline__ void epi_store64(int m0, int n0, float acc[4][4],
                                            const float* biasV, float* outF, int ldo) {
    const int tid = threadIdx.x;
    const int w = tid >> 5, l = tid & 31;
    const int wg = w >> 2, wm = w & 3;
    const int r = l >> 2, c2 = (l & 3) * 2;
#pragma unroll
    for (int j = 0; j < 4; ++j) {
        int n = n0 + wg * 32 + 8 * j + c2;
        float bv0 = biasV[n], bv1 = biasV[n + 1];
        size_t row0 = (size_t)(m0 + 16 * wm + r);
        outF[row0 * ldo + n] = acc[j][0] + bv0;
        outF[row0 * ldo + n + 1] = acc[j][1] + bv1;
        outF[(row0 + 8) * ldo + n] = acc[j][2] + bv0;
        outF[(row0 + 8) * ldo + n + 1] = acc[j][3] + bv1;
    }
}

__device__ __forceinline__ void epi_lstm64(char* smem, int n0, float acc[4][4],
                                           const float* biasM1, const float* biasM2,
                                           int streamBias,
                                           bf16* outHL, float* outF, float* cstate) {
    const int tid = threadIdx.x;
    const int w = tid >> 5, l = tid & 31;
    const int wg = w >> 2, wm = w & 3;
    const int r = l >> 2, c2 = (l & 3) * 2;
    float* Csm = (float*)smem;
#pragma unroll
    for (int j = 0; j < 4; ++j) {
        int col = wg * 32 + 8 * j + c2;
        int n = n0 + col;
#pragma unroll
        for (int hh = 0; hh < 2; ++hh) {
            int m = 16 * wm + r + hh * 8;
            float b0, b1;
            if (streamBias) {
                b0 = __ldcs(&biasM1[(size_t)m * 4096 + n]);
                b1 = __ldcs(&biasM1[(size_t)m * 4096 + n + 1]);
            } else {
                b0 = __ldcg(&biasM1[(size_t)m * 4096 + n]);
                b1 = __ldcg(&biasM1[(size_t)m * 4096 + n + 1]);
            }
            if (biasM2) {
                b0 += __ldcg(&biasM2[(size_t)m * 4096 + n]);
                b1 += __ldcg(&biasM2[(size_t)m * 4096 + n + 1]);
            }
            Csm[m * 65 + col] = acc[j][2 * hh] + b0;
            Csm[m * 65 + col + 1] = acc[j][2 * hh + 1] + b1;
        }
    }
    __syncthreads();
#pragma unroll
    for (int q = 0; q < 4; ++q) {
        int item = tid * 4 + q;
        int b = item >> 4;
        int hu = item & 15;
        float gi = Csm[b * 65 + hu * 4 + 0];
        float gf = Csm[b * 65 + hu * 4 + 1];
        float gg = Csm[b * 65 + hu * 4 + 2];
        float go = Csm[b * 65 + hu * 4 + 3];
        int hg = (n0 >> 2) + hu;
        int idx = b * HDIM + hg;
        float cold = cstate[idx];
        float i_ = sigm(gi), f_ = sigm(gf), g_ = tanhf(gg), o_ = sigm(go);
        float cn = f_ * cold + i_ * g_;
        cstate[idx] = cn;
        float hv = o_ * tanhf(cn);
        if (outF) outF[idx] = hv;
        bf16 hi = __float2bfloat16(hv);
        bf16 lo = __float2bfloat16(hv - __bfloat162float(hi));
        outHL[b * 2048 + hg] = hi;
        outHL[b * 2048 + 1024 + hg] = lo;
    }
    __syncthreads();
}

__device__ __forceinline__ void epi_tanh_c(int n0, float acc[4][4], const float* cpartM,
                                           float* outF, int ldo, bf16* outHL) {
    const int tid = threadIdx.x;
    const int w = tid >> 5, l = tid & 31;
    const int wg = w >> 2, wm = w & 3;
    const int r = l >> 2, c2 = (l & 3) * 2;
#pragma unroll
    for (int j = 0; j < 4; ++j) {
        int n = n0 + wg * 32 + 8 * j + c2;
        int b0r = 16 * wm + r;
#pragma unroll
        for (int hh = 0; hh < 2; ++hh) {
            int bb = b0r + hh * 8;
            float p0 = __ldcg(&cpartM[(size_t)bb * 1024 + n]);
            float p1 = __ldcg(&cpartM[(size_t)bb * 1024 + n + 1]);
            float v0 = tanhf(acc[j][2 * hh] + p0);
            float v1 = tanhf(acc[j][2 * hh + 1] + p1);
            __stcs(&outF[(size_t)bb * ldo + n], v0);
            __stcs(&outF[(size_t)bb * ldo + n + 1], v1);
            bf16 h0 = __float2bfloat16(v0);
            bf16 l0 = __float2bfloat16(v0 - __bfloat162float(h0));
            bf16 h1 = __float2bfloat16(v1);
            bf16 l1 = __float2bfloat16(v1 - __bfloat162float(h1));
            outHL[bb * 2048 + n] = h0;
            outHL[bb * 2048 + 1024 + n] = l0;
            outHL[bb * 2048 + n + 1] = h1;
            outHL[bb * 2048 + 1024 + n + 1] = l1;
        }
    }
}

// ---------------- attention (cp.async pipelined) ----------------
#define ATT_STG 32768
__device__ __forceinline__ void attn_dev(char* smem, int b,
                                         const int* __restrict__ masks,
                                         const float* __restrict__ encproj,
                                         const float* __restrict__ enc,
                                         const float* __restrict__ h2f,
                                         bf16* __restrict__ athl) {
    float* sh2 = (float*)(smem + 3 * ATT_STG);
    float* sred = (float*)(smem + 3 * ATT_STG + 4096);
    float* salpha = sred + LLEN;
    float* stmp = salpha + LLEN;
    const int tid = threadIdx.x;
    const int w = tid >> 5, l = tid & 31;
    const uint32_t sB = (uint32_t)__cvta_generic_to_shared(smem);

    {
        const float4* src = (const float4*)(h2f + b * HDIM);
        ((float4*)sh2)[tid] = __ldcg(src + tid);
    }

    const char* epbase = (const char*)(encproj + (size_t)b * LLEN * HDIM);
    auto issueS = [&](int s) {
        const uint32_t base = sB + (s % 3) * ATT_STG;
        const char* src = epbase + (size_t)s * ATT_STG;
#pragma unroll
        for (int i = 0; i < 8; ++i) {
            int c = tid + (i << 8);
            CP16(base + c * 16, src + c * 16);
        }
        asm volatile("cp.async.commit_group;\n" ::);
    };
    issueS(0); issueS(1); issueS(2);
    __syncthreads();

    const float4* sh4 = (const float4*)sh2;
    for (int s = 0; s < 16; ++s) {
        if (s <= 13)      asm volatile("cp.async.wait_group 2;\n" ::);
        else if (s == 14) asm volatile("cp.async.wait_group 1;\n" ::);
        else              asm volatile("cp.async.wait_group 0;\n" ::);
        __syncthreads();
        const float4* row = (const float4*)(smem + (s % 3) * ATT_STG + w * 4096);
        float sdot = 0.f;
#pragma unroll
        for (int j = 0; j < 8; ++j) {
            float4 hv = sh4[l + 32 * j];
            float4 ev = row[l + 32 * j];
            sdot += hv.x * ev.x + hv.y * ev.y + hv.z * ev.z + hv.w * ev.w;
        }
#pragma unroll
        for (int o = 16; o; o >>= 1) sdot += __shfl_xor_sync(0xffffffffu, sdot, o);
        if (l == 0) sred[s * 8 + w] = sdot;
        __syncthreads();
        if (s + 3 < 16) issueS(s + 3);
    }

    if (tid < 128) {
        float v = masks[b * LLEN + tid] ? -1e30f : sred[tid];
        sred[tid] = v;
        stmp[tid] = v;
    }
    __syncthreads();
    for (int s = 64; s; s >>= 1) {
        if (tid < s) stmp[tid] = fmaxf(stmp[tid], stmp[tid + s]);
        __syncthreads();
    }
    const float mx = stmp[0];
    __syncthreads();
    if (tid < 128) {
        float p = __expf(sred[tid] - mx);
        salpha[tid] = p;
        stmp[tid] = p;
    }
    __syncthreads();
    for (int s = 64; s; s >>= 1) {
        if (tid < s) stmp[tid] += stmp[tid + s];
        __syncthreads();
    }
    const float inv = 1.f / stmp[0];
    __syncthreads();
    if (tid < 128) salpha[tid] *= inv;
    __syncthreads();

    const char* enbase = (const char*)(enc + (size_t)b * LLEN * HEDIM);
    auto issueC = [&](int s) {
        const uint32_t base = sB + (s % 3) * ATT_STG;
        const char* src = enbase + (size_t)s * ATT_STG;
#pragma unroll
        for (int i = 0; i < 8; ++i) {
            int c = tid + (i << 8);
            CP16(base + c * 16, src + c * 16);
        }
        asm volatile("cp.async.commit_group;\n" ::);
    };
    issueC(0); issueC(1); issueC(2);

    float4 accv = make_float4(0.f, 0.f, 0.f, 0.f);
    for (int s = 0; s < 16; ++s) {
        if (s <= 13)      asm volatile("cp.async.wait_group 2;\n" ::);
        else if (s == 14) asm volatile("cp.async.wait_group 1;\n" ::);
        else              asm volatile("cp.async.wait_group 0;\n" ::);
        __syncthreads();
        const float4* stage4 = (const float4*)(smem + (s % 3) * ATT_STG);
#pragma unroll
        for (int rrow = 0; rrow < 8; ++rrow) {
            float al = salpha[s * 8 + rrow];
            float4 v = stage4[rrow * 256 + tid];
            accv.x += al * v.x;
            accv.y += al * v.y;
            accv.z += al * v.z;
            accv.w += al * v.w;
        }
        __syncthreads();
        if (s + 3 < 16) issueC(s + 3);
    }

    int f = tid * 4;
    float vals[4] = {accv.x, accv.y, accv.z, accv.w};
#pragma unroll
    for (int i = 0; i < 4; ++i) {
        bf16 hi = __float2bfloat16(vals[i]);
        bf16 lo = __float2bfloat16(vals[i] - __bfloat162float(hi));
        athl[b * 2048 + f + i] = hi;
        athl[b * 2048 + 1024 + f + i] = lo;
    }
    __syncthreads();
}

// ---------------- grid barrier ----------------
__device__ __forceinline__ void gsync(int slot) {
    __threadfence();
    __syncthreads();
    if (threadIdx.x == 0) {
        unsigned g = ((volatile unsigned*)g_gen)[slot];
        unsigned old = atomicAdd(&g_cnt[slot], 1u);
        if (old == NCTA - 1) {
            g_cnt[slot] = 0;
            __threadfence();
            atomicExch(&g_gen[slot], g + 1);
        } else {
            while (((volatile unsigned*)g_gen)[slot] == g) __nanosleep(32);
        }
    }
    __syncthreads();
    __threadfence();
}

// ---------------- prologue GEMM ----------------
__global__ __launch_bounds__(256) void mma_pro(
    const bf16* A0, const bf16* W0, int K0,
    const float* __restrict__ biasV, float* __restrict__ outF, int ldo) {
    extern __shared__ __align__(16) char smem[];
    float acc[4][4];
    gemm64(smem, blockIdx.y * 64, blockIdx.x * 64, A0, W0, K0, acc);
    epi_store64(blockIdx.y * 64, blockIdx.x * 64, acc, biasV, outF, ldo);
}

// ---------------- step-phase helpers ----------------
__device__ __forceinline__ void lstm1_tile(char* smem, int tp, int tile) {
    float acc[4][4];
    int n0 = tile * 64;
    gemm64(smem, 0, n0, g_h1hl[tp & 1], g_Whh1, 1024, acc);
    epi_lstm64(smem, n0, acc, g_pregates + (size_t)tp * BBATCH * 4096, nullptr, 1,
               g_h1hl[(tp & 1) ^ 1], nullptr, g_c1);
}

__device__ __forceinline__ void lstm2_pair1(char* smem, int tp, int tile) {
    float acc[4][4];
    int n0 = tile * 64;
    gemm64(smem, 0, n0, g_h1hl[(tp & 1) ^ 1], g_Wih2A, 1024, acc);
    epi_store64(0, n0, acc, g_bg2, g_gpartA, 4096);
}

__device__ __forceinline__ void lstm2_pair2(char* smem, int tp, int tile) {
    float acc[4][4];
    int n0 = tile * 64;
    gemm64(smem, 0, n0, g_h2hl[tp & 1], g_Whh2, 1024, acc);
    epi_store64(0, n0, acc, g_zero, g_gpartB, 4096);
}

__device__ __forceinline__ void lstm2_final(char* smem, int t, int tile) {
    float acc[4][4];
    int n0 = tile * 64;
    gemm64(smem, 0, n0, g_ohl, g_Wih2B, 1024, acc);
    epi_lstm64(smem, n0, acc, g_gpartA, g_gpartB, 0, g_h2hl[(t + 1) & 1], g_h2f, g_c2);
}

__device__ __forceinline__ void comb_partial_b(char* smem, int t, int tile,
                                               const float* b_comb) {
    float acc[4][4];
    int n0 = tile * 64;
    gemm64(smem, 0, n0, g_h2hl[(t + 1) & 1], g_WcmB, 1024, acc);
    epi_store64(0, n0, acc, b_comb, g_cpart, 1024);
}

__device__ __forceinline__ void comb_final(char* smem, int t, int tile, float* outs) {
    float acc[4][4];
    int n0 = tile * 64;
    gemm64(smem, 0, n0, g_athl, g_WcmA, 1024, acc);
    epi_tanh_c(n0, acc, g_cpart, outs + (size_t)t * BBATCH * HDIM, 1024, g_ohl);
}

// ---------------- persistent decoder loop ----------------
__global__ __launch_bounds__(256, 1) void decoder_loop(
    const int* __restrict__ masks, const float* __restrict__ enc,
    const float* __restrict__ b_comb, float* __restrict__ outs) {
    extern __shared__ __align__(16) char smem[];
    const int bid = blockIdx.x;

    if (bid < 64) lstm1_tile(smem, 0, bid);
    gsync(0);
    if (bid < 64) lstm2_pair1(smem, 0, bid);
    else if (bid < 128) lstm2_pair2(smem, 0, bid - 64);
    gsync(1);

    for (int t = 0; t < TSTEPS; ++t) {
        // PHASE A: lstm2_final@t (0-63) || lstm1@t+1 (64-127)
        if (bid < 64) {
            lstm2_final(smem, t, bid);
        } else if (bid < 128 && t + 1 < TSTEPS) {
            lstm1_tile(smem, t + 1, bid - 64);
        }
        gsync(2 + t * 3);

        // PHASE B: attn@t (0-63, full bandwidth) || comb-partial@t (128-143)
        if (bid < 64) {
            attn_dev(smem, bid, masks, g_encproj, enc, g_h2f, g_athl);
        } else if (bid >= 128 && bid < 144) {
            comb_partial_b(smem, t, bid - 128, b_comb);
        }
        gsync(3 + t * 3);

        // PHASE C: comb-final@t (0-15) || pair1@t+1 (16-79) || pair2@t+1 (80-143)
        if (bid < 16) {
            comb_final(smem, t, bid, outs);
        } else if (bid < 80) {
            if (t + 1 < TSTEPS) lstm2_pair1(smem, t + 1, bid - 16);
        } else if (bid < 144) {
            if (t + 1 < TSTEPS) lstm2_pair2(smem, t + 1, bid - 80);
        }
        gsync(4 + t * 3);
    }
}

// ---------------- host launcher ----------------
extern "C" void kernel_launch(void* const* d_in, const int* in_sizes, int n_in,
                              void* d_out, int out_size) {
    const float* enc = (const float*)d_in[0];
    const int* masks = (const int*)d_in[1];
    const float* h1i = (const float*)d_in[2];
    const float* c1i = (const float*)d_in[3];
    const float* h2i = (const float*)d_in[4];
    const float* c2i = (const float*)d_in[5];
    const float* cap = (const float*)d_in[6];
    const float* W_ih1 = (const float*)d_in[7];
    const float* W_hh1 = (const float*)d_in[8];
    const float* b_ih1 = (const float*)d_in[9];
    const float* b_hh1 = (const float*)d_in[10];
    const float* W_ih2 = (const float*)d_in[11];
    const float* W_hh2 = (const float*)d_in[12];
    const float* b_ih2 = (const float*)d_in[13];
    const float* b_hh2 = (const float*)d_in[14];
    const float* W_att = (const float*)d_in[15];
    const float* b_att = (const float*)d_in[16];
    const float* W_comb = (const float*)d_in[17];
    const float* b_comb = (const float*)d_in[18];
    float* outs = (float*)d_out;

    bf16 *pWih1, *pWatt, *pEnchl, *pCapshl;
    float *pEncproj, *pPre, *pBg1;
    cudaGetSymbolAddress((void**)&pWih1, g_Wih1);
    cudaGetSymbolAddress((void**)&pWatt, g_Watt);
    cudaGetSymbolAddress((void**)&pEnchl, g_enchl);
    cudaGetSymbolAddress((void**)&pCapshl, g_capshl);
    cudaGetSymbolAddress((void**)&pEncproj, g_encproj);
    cudaGetSymbolAddress((void**)&pPre, g_pregates);
    cudaGetSymbolAddress((void**)&pBg1, g_bg1);

    const int SMEM = NSTG * STGB;   // 128 KB
    cudaFuncSetAttribute(mma_pro, cudaFuncAttributeMaxDynamicSharedMemorySize, SMEM);
    cudaFuncSetAttribute(decoder_loop, cudaFuncAttributeMaxDynamicSharedMemorySize, SMEM);

    conv_all<<<CONV_BLOCKS, 256>>>(enc, cap, W_ih1, W_hh1, W_ih2, W_hh2, W_comb, W_att,
                                   b_ih1, b_hh1, b_ih2, b_hh2, h1i, c1i, h2i, c2i);

    mma_pro<<<dim3(64, 48), 256, SMEM>>>(pCapshl, pWih1, 512, pBg1, pPre, 4096);
    mma_pro<<<dim3(16, 128), 256, SMEM>>>(pEnchl, pWatt, 1024, b_att, pEncproj, 1024);

    decoder_loop<<<NCTA, 256, SMEM>>>(masks, enc, b_comb, outs);
}